// round 10
// baseline (speedup 1.0000x reference)
#include <cuda_runtime.h>
#include <cstdint>

#define NH 12
#define DH 64
#define SEQ 512
#define DM 768
#define MAXB 32

typedef unsigned long long u64;

// ============================ PTX helpers ============================
__device__ __forceinline__ float tf32r(float x) {
    float r; asm("cvt.rna.tf32.f32 %0, %1;" : "=f"(r) : "f"(x)); return r;
}
__device__ __forceinline__ void mma8(float* c, const uint32_t* a, const uint32_t* b) {
    asm volatile(
        "mma.sync.aligned.m16n8k8.row.col.f32.tf32.tf32.f32 "
        "{%0,%1,%2,%3}, {%4,%5,%6,%7}, {%8,%9}, {%0,%1,%2,%3};"
        : "+f"(c[0]), "+f"(c[1]), "+f"(c[2]), "+f"(c[3])
        : "r"(a[0]), "r"(a[1]), "r"(a[2]), "r"(a[3]), "r"(b[0]), "r"(b[1]));
}
__device__ __forceinline__ uint32_t fbits(float x) { return __float_as_uint(x); }
__device__ __forceinline__ uint32_t smem_u32(const void* p) {
    uint32_t a;
    asm("{ .reg .u64 t; cvta.to.shared.u64 t, %1; cvt.u32.u64 %0, t; }" : "=r"(a) : "l"(p));
    return a;
}
__device__ __forceinline__ void cpa16(uint32_t s, const float* g) {
    asm volatile("cp.async.cg.shared.global [%0], [%1], 16;" :: "r"(s), "l"(g));
}
__device__ __forceinline__ void cpa_commit() {
    asm volatile("cp.async.commit_group;" ::: "memory");
}
template<int N>
__device__ __forceinline__ void cpa_wait() {
    asm volatile("cp.async.wait_group %0;" :: "n"(N) : "memory");
}

// d-perm within 8-groups: swap so (k, k+4) become adjacent
__device__ __forceinline__ int dperm(int d) {
    return (d & ~7) | (((d & 3) << 1) | ((d >> 2) & 1));
}

// ============================ device scratch ============================
__device__ float g_q[(size_t)MAXB * NH * SEQ * DH];     // tf32, d-permuted
__device__ float g_k[(size_t)MAXB * NH * SEQ * DH];     // tf32, d-permuted
__device__ float g_vt[(size_t)MAXB * NH * DH * SEQ];    // tf32, [d][s], mask folded
__device__ float g_aht[(size_t)DM * MAXB * SEQ];        // hidden^T [k][m_perm], tf32
__device__ float g_wth[(size_t)3 * DM * DM];            // W^T [mat][n][kperm], tf32

// ---------------------------------------------------------------------------
__global__ void htrans_kernel(const float* __restrict__ h, int M) {
    __shared__ float t[32][33];
    const int m0 = blockIdx.x * 32, k0 = blockIdx.y * 32;
    const int tx = threadIdx.x, ty = threadIdx.y;
#pragma unroll
    for (int j = 0; j < 32; j += 8)
        t[ty + j][tx] = tf32r(h[(size_t)(m0 + ty + j) * DM + k0 + tx]);
    __syncthreads();
    const int m = m0 + tx;
    const int mp = (m & ~15) | (((m & 7) << 1) | ((m >> 3) & 1));
#pragma unroll
    for (int j = 0; j < 32; j += 8)
        g_aht[(size_t)(k0 + ty + j) * M + mp] = t[tx][ty + j];
}

// W transpose with k-permutation baked (for LDS.64 B fragments)
__global__ void wsplit_kernel(const float* __restrict__ Wq,
                              const float* __restrict__ Wk,
                              const float* __restrict__ Wv) {
    __shared__ float th[32][33];
    int mat = blockIdx.z;
    const float* W = (mat == 0) ? Wq : ((mat == 1) ? Wk : Wv);
    int k0 = blockIdx.y * 32, n0 = blockIdx.x * 32;
    int tx = threadIdx.x, ty = threadIdx.y;
#pragma unroll
    for (int j = 0; j < 32; j += 8)
        th[ty + j][tx] = tf32r(W[(size_t)(k0 + ty + j) * DM + n0 + tx]);
    __syncthreads();
    float* oh = g_wth + (size_t)mat * DM * DM;
#pragma unroll
    for (int j = 0; j < 32; j += 8)
        oh[(size_t)(n0 + ty + j) * DM + dperm(k0 + tx)] = th[tx][ty + j];
}

// ---------------------------------------------------------------------------
// Unified QKV GEMM: CTA 128x128, 4 warps as 2(m) x 2(n), warp 64x64.
// A: k-major swizzled (LDS.64). B: [n][kperm] pad-40 (LDS.64). NSTG=3.
// Epilogue: Q/K tf32+dperm scatter; V -> tf32, mask-multiplied, transposed.
// ---------------------------------------------------------------------------
#define ASTAGE_F 4096
#define BSTAGE_F (128 * 40)
#define NSTG 3
#define GEMM_SMEM ((NSTG * (ASTAGE_F + BSTAGE_F)) * 4)   // 110592 B

__global__ __launch_bounds__(128, 2) void qkv_gemm_kernel(
    const float* __restrict__ bq, const float* __restrict__ bk,
    const float* __restrict__ bv, const float* __restrict__ mask, int M)
{
    extern __shared__ float sm[];
    float* Bbase = sm + NSTG * ASTAGE_F;

    const int tid  = threadIdx.x;
    const int lane = tid & 31;
    const int wid  = tid >> 5;
    const int wm   = wid >> 1;       // 0..1 -> 64 m-rows
    const int wn   = wid & 1;        // 0..1 -> 64 n-cols
    const int lr   = lane >> 2;
    const int lc   = lane & 3;

    const int m0  = blockIdx.x * 128;
    const int yb  = blockIdx.y;
    const int mat = yb / 6;
    const int n0  = (yb % 6) * 128;

    const float* Wh = g_wth + (size_t)mat * DM * DM + (size_t)n0 * DM;

    // A load: k-row tid>>2 (0..31), m-seg (tid&3)*32 (8 cpa16)
    const int ak   = tid >> 2;
    const int ams  = (tid & 3) * 32;
    const float* gA = g_aht + (size_t)ak * M + m0 + ams;
    // B load: one n-row per thread (32 floats = 8 cpa16), kperm in gmem
    const float* gB = Wh + (size_t)tid * DM;

    const uint32_t sbA = smem_u32(sm);
    const uint32_t sbB = smem_u32(Bbase);
    const uint32_t aXor = (uint32_t)((ak & 3) << 1);
    const uint32_t aRow = (uint32_t)ak * 512;
    const uint32_t bOff = (uint32_t)(tid * 40) * 4;

#define ISSUE(ch, st)                                                         \
    do {                                                                      \
        const float* _a = gA + (size_t)(ch) * 32 * M;                         \
        const float* _b = gB + (ch) * 32;                                     \
        uint32_t _sa = sbA + (st) * (ASTAGE_F * 4) + aRow;                    \
        uint32_t _sb = sbB + (st) * (BSTAGE_F * 4) + bOff;                    \
        _Pragma("unroll")                                                     \
        for (int _i = 0; _i < 8; _i++) {                                      \
            uint32_t _blk = (uint32_t)((ams >> 2) + _i) ^ aXor;               \
            cpa16(_sa + _blk * 16, _a + _i * 4);                              \
            cpa16(_sb + _i * 16, _b + _i * 4);                                \
        }                                                                     \
    } while (0)

    float c[4][8][4];
#pragma unroll
    for (int i = 0; i < 4; i++)
#pragma unroll
        for (int j = 0; j < 8; j++)
#pragma unroll
            for (int q = 0; q < 4; q++) c[i][j][q] = 0.0f;

    const int NCH = DM / 32;   // 24

#pragma unroll
    for (int p = 0; p < NSTG - 1; p++) {
        ISSUE(p, p);
        cpa_commit();
    }

    for (int ch = 0; ch < NCH; ch++) {
        const int pre = ch + NSTG - 1;
        if (pre < NCH) ISSUE(pre, pre % NSTG);
        cpa_commit();
        cpa_wait<NSTG - 1>();
        __syncthreads();

        const int st = ch % NSTG;
        const float* As = sm + st * ASTAGE_F;
        const float* Bs = Bbase + st * BSTAGE_F;

#pragma unroll
        for (int ks = 0; ks < 4; ks++) {
            const int kc = ks * 8;
            uint32_t ah[4][4];
#pragma unroll
            for (int mt = 0; mt < 4; mt++) {
                const int wl = wm * 64 + mt * 16;
                const uint32_t bXor = (uint32_t)(lc << 1);
                const uint32_t blk = (uint32_t)((wl >> 2) + (lr >> 1)) ^ bXor;
                const uint32_t fo  = (uint32_t)((lr & 1) * 2);
                float2 p01 = *(const float2*)(As + (kc + lc) * 128 + blk * 4 + fo);
                float2 p23 = *(const float2*)(As + (kc + 4 + lc) * 128 + blk * 4 + fo);
                ah[mt][0] = fbits(p01.x); ah[mt][1] = fbits(p01.y);
                ah[mt][2] = fbits(p23.x); ah[mt][3] = fbits(p23.y);
            }
            uint32_t bh[8][2];
#pragma unroll
            for (int nt = 0; nt < 8; nt++) {
                const int nb = wn * 64 + nt * 8;
                float2 b2 = *(const float2*)&Bs[(nb + lr) * 40 + kc + 2 * lc];
                bh[nt][0] = fbits(b2.x); bh[nt][1] = fbits(b2.y);
            }
#pragma unroll
            for (int mt = 0; mt < 4; mt++)
#pragma unroll
                for (int nt = 0; nt < 8; nt++)
                    mma8(c[mt][nt], ah[mt], bh[nt]);
        }
        __syncthreads();
    }
#undef ISSUE

    // epilogue
    const float* bias = (mat == 0) ? bq : ((mat == 1) ? bk : bv);
    float* dstqk      = (mat == 0) ? g_q : g_k;
    const bool rqk    = (mat != 2);
#pragma unroll
    for (int mt = 0; mt < 4; mt++) {
        const int m = m0 + wm * 64 + mt * 16 + lr;
#pragma unroll
        for (int nt = 0; nt < 8; nt++) {
            const int n = n0 + wn * 64 + nt * 8 + 2 * lc;
            const int hh = n >> 6, d = n & 63;
            const float b0 = bias[n], b1 = bias[n + 1];
#pragma unroll
            for (int half = 0; half < 2; half++) {
                const int mm = m + half * 8;
                const int bi = mm >> 9, srow = mm & 511;
                float v0 = c[mt][nt][half * 2 + 0] + b0;
                float v1 = c[mt][nt][half * 2 + 1] + b1;
                if (rqk) {
                    float* o = dstqk + (((size_t)(bi * NH + hh)) * SEQ + srow) * DH;
                    o[dperm(d)]     = tf32r(v0);
                    o[dperm(d + 1)] = tf32r(v1);
                } else {
                    const float mv = mask[(size_t)bi * SEQ + srow];
                    float* o = g_vt + ((size_t)(bi * NH + hh) * DH) * SEQ;
                    o[(size_t)d * SEQ + srow]       = tf32r(v0 * mv);
                    o[(size_t)(d + 1) * SEQ + srow] = tf32r(v1 * mv);
                }
            }
        }
    }
}

// ---------------------------------------------------------------------------
// Fused power-law attention: 4 warps x 32 q-rows (q-tile 128), key-tile 32,
// double-buffered cp.async. Q in registers; phase1 accs feed phase2 A-frags
// via key-perm mapping; V consumed transposed [d][s], frags shared across mt.
// ---------------------------------------------------------------------------
#define KT 32
#define PADK 72
#define PADV 40
#define KBUF_F (KT * PADK)
#define VBUF_F (DH * PADV)

__global__ __launch_bounds__(128, 2) void attn_kernel(float* __restrict__ out)
{
    __shared__ float Ks[2][KBUF_F];
    __shared__ float Vs[2][VBUF_F];

    const int b  = blockIdx.z;
    const int h  = blockIdx.y;
    const int qt = blockIdx.x * 128;

    const float* Qg = g_q + (((size_t)(b * NH + h)) * SEQ + qt) * DH;
    const float* Kg = g_k + ((size_t)(b * NH + h)) * SEQ * DH;
    const float* Vg = g_vt + ((size_t)(b * NH + h)) * DH * SEQ;   // [d][s]

    const int tid  = threadIdx.x;
    const int lane = tid & 31;
    const int wid  = tid >> 5;      // 0..3 -> 32 q-rows each
    const int lr   = lane >> 2;
    const int lc   = lane & 3;

    // cp.async mappings (128 threads)
    const int krow = tid >> 2;              // 0..31 keys
    const int ksg  = (tid & 3) * 16;        // d segment (4 cpa16)
    const float* KgR = Kg + (size_t)krow * DH + ksg;
    const uint32_t sK = smem_u32(&Ks[0][0]) + (uint32_t)(krow * PADK + ksg) * 4;

    const int vrow = tid >> 1;              // 0..63 d
    const int vsg  = (tid & 1) * 16;        // key segment (4 cpa16)
    const float* VgR = Vg + (size_t)vrow * SEQ + vsg;
    const uint32_t sV = smem_u32(&Vs[0][0]) + (uint32_t)(vrow * PADV + vsg) * 4;

#define ISSKV(kt_, buf_)                                                      \
    do {                                                                      \
        const float* _k = KgR + (size_t)(kt_) * KT * DH;                      \
        const float* _v = VgR + (kt_) * KT;                                   \
        uint32_t _ok = (uint32_t)(buf_) * (KBUF_F * 4);                       \
        uint32_t _ov = (uint32_t)(buf_) * (VBUF_F * 4);                       \
        _Pragma("unroll")                                                     \
        for (int _i = 0; _i < 4; _i++) {                                      \
            cpa16(sK + _ok + _i * 16, _k + _i * 4);                           \
            cpa16(sV + _ov + _i * 16, _v + _i * 4);                           \
        }                                                                     \
        cpa_commit();                                                         \
    } while (0)

    ISSKV(0, 0);

    // Q fragments: 32 rows per warp (2 m-tiles), register-resident
    float2 qf[2][2][8];   // [mt][half][ks]
    {
#pragma unroll
        for (int mt = 0; mt < 2; mt++) {
            const int r0 = wid * 32 + mt * 16 + lr;
#pragma unroll
            for (int ks = 0; ks < 8; ks++) {
                qf[mt][0][ks] = *(const float2*)(Qg + (size_t)r0 * DH + ks * 8 + 2 * lc);
                qf[mt][1][ks] = *(const float2*)(Qg + (size_t)(r0 + 8) * DH + ks * 8 + 2 * lc);
            }
        }
    }

    float o[2][8][4];
#pragma unroll
    for (int i = 0; i < 2; i++)
#pragma unroll
        for (int j = 0; j < 8; j++)
#pragma unroll
            for (int q = 0; q < 4; q++) o[i][j][q] = 0.0f;
    float den[2][2] = {{0.0f, 0.0f}, {0.0f, 0.0f}};   // [mt][row/row+8]

    const int NKT = SEQ / KT;   // 16

    for (int kt = 0; kt < NKT; kt++) {
        const int buf = kt & 1;
        if (kt + 1 < NKT) {
            ISSKV(kt + 1, buf ^ 1);
            cpa_wait<1>();
        } else {
            cpa_wait<0>();
        }
        __syncthreads();

        const float* Kb = Ks[buf];
        const float* Vb = Vs[buf];

        // ---- phase 1: S = Q K^T ----
        float s[2][4][4];
#pragma unroll
        for (int i = 0; i < 2; i++)
#pragma unroll
            for (int j = 0; j < 4; j++)
#pragma unroll
                for (int q = 0; q < 4; q++) s[i][j][q] = 0.0f;

#pragma unroll
        for (int ks = 0; ks < 8; ks++) {
            uint32_t a[2][4];
#pragma unroll
            for (int mt = 0; mt < 2; mt++) {
                a[mt][0] = fbits(qf[mt][0][ks].x); a[mt][1] = fbits(qf[mt][1][ks].x);
                a[mt][2] = fbits(qf[mt][0][ks].y); a[mt][3] = fbits(qf[mt][1][ks].y);
            }
#pragma unroll
            for (int nt = 0; nt < 4; nt++) {
                float2 k2 = *(const float2*)&Kb[(nt * 8 + lr) * PADK + ks * 8 + 2 * lc];
                uint32_t bbf[2] = {fbits(k2.x), fbits(k2.y)};
                mma8(s[0][nt], a[0], bbf);
                mma8(s[1][nt], a[1], bbf);
            }
        }

        // ---- transform + phase 2 ----
#pragma unroll
        for (int nt = 0; nt < 4; nt++) {
            uint32_t af[2][4];
#pragma unroll
            for (int mt = 0; mt < 2; mt++) {
                float t0 = fmaf(s[mt][nt][0], 0.125f, 5.0f);
                float t1 = fmaf(s[mt][nt][1], 0.125f, 5.0f);
                float t2 = fmaf(s[mt][nt][2], 0.125f, 5.0f);
                float t3 = fmaf(s[mt][nt][3], 0.125f, 5.0f);
                float u0 = tf32r(t0 * t0);
                float u1 = tf32r(t1 * t1);
                float u2 = tf32r(t2 * t2);
                float u3 = tf32r(t3 * t3);
                den[mt][0] += u0 + u1;
                den[mt][1] += u2 + u3;
                af[mt][0] = fbits(u0); af[mt][1] = fbits(u2);
                af[mt][2] = fbits(u1); af[mt][3] = fbits(u3);
            }
#pragma unroll
            for (int dt = 0; dt < 8; dt++) {
                float2 v2 = *(const float2*)&Vb[(dt * 8 + lr) * PADV + nt * 8 + 2 * lc];
                uint32_t bv[2] = {fbits(v2.x), fbits(v2.y)};
                mma8(o[0][dt], af[0], bv);
                mma8(o[1][dt], af[1], bv);
            }
        }
        __syncthreads();
    }
#undef ISSKV

    // quad-reduce den
#pragma unroll
    for (int mt = 0; mt < 2; mt++)
#pragma unroll
        for (int j = 0; j < 2; j++) {
            float v = den[mt][j];
            v += __shfl_xor_sync(0xFFFFFFFFu, v, 1);
            v += __shfl_xor_sync(0xFFFFFFFFu, v, 2);
            den[mt][j] = v;
        }

#pragma unroll
    for (int mt = 0; mt < 2; mt++) {
        const float inv0 = 1.0f / (den[mt][0] + 1e-10f);
        const float inv1 = 1.0f / (den[mt][1] + 1e-10f);
        const int r0 = qt + wid * 32 + mt * 16 + lr;
        float* o0 = out + ((size_t)b * SEQ + r0) * DM + h * DH;
        float* o1 = out + ((size_t)b * SEQ + r0 + 8) * DM + h * DH;
#pragma unroll
        for (int dt = 0; dt < 8; dt++) {
            const int d = dt * 8 + 2 * lc;
            *(float2*)(o0 + d) = make_float2(o[mt][dt][0] * inv0, o[mt][dt][1] * inv0);
            *(float2*)(o1 + d) = make_float2(o[mt][dt][2] * inv1, o[mt][dt][3] * inv1);
        }
    }
}

// ---------------------------------------------------------------------------
extern "C" void kernel_launch(void* const* d_in, const int* in_sizes, int n_in,
                              void* d_out, int out_size)
{
    const float* hidden = (const float*)d_in[0];
    const float* mask   = (const float*)d_in[1];
    const float* Wq     = (const float*)d_in[2];
    const float* bq     = (const float*)d_in[3];
    const float* Wk     = (const float*)d_in[4];
    const float* bk     = (const float*)d_in[5];
    const float* Wv     = (const float*)d_in[6];
    const float* bv     = (const float*)d_in[7];
    float* out = (float*)d_out;

    const int BS = in_sizes[1];
    const int B  = BS / SEQ;
    const int M  = BS;

    cudaFuncSetAttribute(qkv_gemm_kernel,
                         cudaFuncAttributeMaxDynamicSharedMemorySize, GEMM_SMEM);

    dim3 gh(M / 32, DM / 32);
    htrans_kernel<<<gh, dim3(32, 8)>>>(hidden, M);

    dim3 gw(DM / 32, DM / 32, 3);
    wsplit_kernel<<<gw, dim3(32, 8)>>>(Wq, Wk, Wv);

    dim3 gm(M / 128, 18);
    qkv_gemm_kernel<<<gm, 128, GEMM_SMEM>>>(bq, bk, bv, mask, M);

    dim3 g2(SEQ / 128, NH, B);
    attn_kernel<<<g2, 128>>>(out);
}

// round 11
// speedup vs baseline: 2.2061x; 2.2061x over previous
#include <cuda_runtime.h>
#include <cuda_fp16.h>
#include <cstdint>

#define NH 12
#define DH 64
#define SEQ 512
#define DM 768
#define MAXB 32

typedef unsigned long long u64;

// ============================ PTX helpers ============================
__device__ __forceinline__ void mma16(float* c, const uint32_t* a, const uint32_t* b) {
    asm volatile(
        "mma.sync.aligned.m16n8k16.row.col.f32.f16.f16.f32 "
        "{%0,%1,%2,%3}, {%4,%5,%6,%7}, {%8,%9}, {%0,%1,%2,%3};"
        : "+f"(c[0]), "+f"(c[1]), "+f"(c[2]), "+f"(c[3])
        : "r"(a[0]), "r"(a[1]), "r"(a[2]), "r"(a[3]), "r"(b[0]), "r"(b[1]));
}
__device__ __forceinline__ uint32_t pkh2(float lo, float hi) {
    __half2 h = __floats2half2_rn(lo, hi);
    return *(uint32_t*)&h;
}
__device__ __forceinline__ uint32_t smem_u32(const void* p) {
    uint32_t a;
    asm("{ .reg .u64 t; cvta.to.shared.u64 t, %1; cvt.u32.u64 %0, t; }" : "=r"(a) : "l"(p));
    return a;
}
__device__ __forceinline__ void cpa16(uint32_t s, const void* g) {
    asm volatile("cp.async.cg.shared.global [%0], [%1], 16;" :: "r"(s), "l"(g));
}
__device__ __forceinline__ void cpa_commit() {
    asm volatile("cp.async.commit_group;" ::: "memory");
}
template<int N>
__device__ __forceinline__ void cpa_wait() {
    asm volatile("cp.async.wait_group %0;" :: "n"(N) : "memory");
}
__device__ __forceinline__ uint32_t lds32h(const __half* p) {
    return *(const uint32_t*)p;
}

// ============================ device scratch ============================
__device__ __align__(128) __half g_q16[(size_t)MAXB * NH * SEQ * DH];   // [s][d]
__device__ __align__(128) __half g_k16[(size_t)MAXB * NH * SEQ * DH];   // [s][d]
__device__ __align__(128) __half g_vt16[(size_t)MAXB * NH * DH * SEQ];  // [d][s], mask folded
__device__ __align__(128) __half g_ah16[(size_t)MAXB * SEQ * DM];       // hidden fp16 [m][k]
__device__ __align__(128) __half g_wth16[(size_t)3 * DM * DM];          // W^T [mat][n][k]

// ---------------------------------------------------------------------------
// hidden -> fp16 (no transpose needed; A consumed m-major)
// ---------------------------------------------------------------------------
__global__ void hhalf_kernel(const float* __restrict__ h, int n8) {
    int i = blockIdx.x * blockDim.x + threadIdx.x;
    if (i >= n8) return;
    float4 x = ((const float4*)h)[2 * i];
    float4 y = ((const float4*)h)[2 * i + 1];
    uint4 o;
    o.x = pkh2(x.x, x.y); o.y = pkh2(x.z, x.w);
    o.z = pkh2(y.x, y.y); o.w = pkh2(y.z, y.w);
    ((uint4*)g_ah16)[i] = o;
}

// ---------------------------------------------------------------------------
// W transpose -> fp16: g_wth16[mat][n][k] = half(W[mat][k][n])
// ---------------------------------------------------------------------------
__global__ void wsplit_kernel(const float* __restrict__ Wq,
                              const float* __restrict__ Wk,
                              const float* __restrict__ Wv) {
    __shared__ float th[32][33];
    int mat = blockIdx.z;
    const float* W = (mat == 0) ? Wq : ((mat == 1) ? Wk : Wv);
    int k0 = blockIdx.y * 32, n0 = blockIdx.x * 32;
    int tx = threadIdx.x, ty = threadIdx.y;
#pragma unroll
    for (int j = 0; j < 32; j += 8)
        th[ty + j][tx] = W[(size_t)(k0 + ty + j) * DM + n0 + tx];
    __syncthreads();
    __half* oh = g_wth16 + (size_t)mat * DM * DM;
#pragma unroll
    for (int j = 0; j < 32; j += 8)
        oh[(size_t)(n0 + ty + j) * DM + k0 + tx] = __float2half(th[tx][ty + j]);
}

// ---------------------------------------------------------------------------
// Unified QKV GEMM, fp16 m16n8k16, cp.async 3-stage pipeline.
// CTA 128x128; 8 warps 2(m) x 4(n); warp 64x32; K-chunk 32 (2 ksteps of k16).
// A smem [m][k] pad-40 halves; B smem [n][k] pad-40 halves. Both conflict-free.
// Epilogue: +bias; Q/K -> fp16 [s][d]; V -> fp16 mask-folded transposed [d][s].
// ---------------------------------------------------------------------------
#define ASTAGE_H (128 * 40)
#define BSTAGE_H (128 * 40)
#define NSTG 3
#define GEMM_SMEM (NSTG * (ASTAGE_H + BSTAGE_H) * 2)    // 61440 B

__global__ __launch_bounds__(256) void qkv_gemm_kernel(
    const float* __restrict__ bq, const float* __restrict__ bk,
    const float* __restrict__ bv, const float* __restrict__ mask, int M)
{
    extern __shared__ __half smh[];
    __half* Abase = smh;
    __half* Bbase = smh + NSTG * ASTAGE_H;

    const int tid  = threadIdx.x;
    const int lane = tid & 31;
    const int wid  = tid >> 5;
    const int wm   = wid >> 2;       // 0..1 -> 64 m-rows
    const int wn   = wid & 3;        // 0..3 -> 32 n-cols
    const int lr   = lane >> 2;
    const int lc   = lane & 3;

    const int m0  = blockIdx.x * 128;
    const int yb  = blockIdx.y;
    const int mat = yb / 6;
    const int n0  = (yb % 6) * 128;

    const __half* Wh = g_wth16 + (size_t)mat * DM * DM + (size_t)n0 * DM;

    // loads: row tid>>1 (0..127), seg (tid&1)*16 halves; 2 cpa16 per tile
    const int arow = tid >> 1;
    const int asel = (tid & 1) * 16;
    const __half* gA = g_ah16 + (size_t)(m0 + arow) * DM + asel;
    const __half* gB = Wh + (size_t)arow * DM + asel;
    const uint32_t sA = smem_u32(Abase) + (uint32_t)(arow * 40 + asel) * 2;
    const uint32_t sB = smem_u32(Bbase) + (uint32_t)(arow * 40 + asel) * 2;

#define ISSUE(ch, st)                                                         \
    do {                                                                      \
        const __half* _a = gA + (ch) * 32;                                    \
        const __half* _b = gB + (ch) * 32;                                    \
        uint32_t _sa = sA + (st) * (ASTAGE_H * 2);                            \
        uint32_t _sb = sB + (st) * (BSTAGE_H * 2);                            \
        cpa16(_sa, _a);      cpa16(_sa + 16, _a + 8);                         \
        cpa16(_sb, _b);      cpa16(_sb + 16, _b + 8);                         \
    } while (0)

    float c[4][4][4];
#pragma unroll
    for (int i = 0; i < 4; i++)
#pragma unroll
        for (int j = 0; j < 4; j++)
#pragma unroll
            for (int q = 0; q < 4; q++) c[i][j][q] = 0.0f;

    const int NCH = DM / 32;   // 24

#pragma unroll
    for (int p = 0; p < NSTG - 1; p++) {
        ISSUE(p, p);
        cpa_commit();
    }

    for (int ch = 0; ch < NCH; ch++) {
        const int pre = ch + NSTG - 1;
        if (pre < NCH) ISSUE(pre, pre % NSTG);
        cpa_commit();
        cpa_wait<NSTG - 1>();
        __syncthreads();

        const int st = ch % NSTG;
        const __half* As = Abase + st * ASTAGE_H;
        const __half* Bs = Bbase + st * BSTAGE_H;

#pragma unroll
        for (int ks = 0; ks < 2; ks++) {
            const int kh = ks * 16;
            uint32_t ah[4][4];
#pragma unroll
            for (int mt = 0; mt < 4; mt++) {
                const int rb = wm * 64 + mt * 16;
                ah[mt][0] = lds32h(&As[(rb + lr) * 40 + kh + 2 * lc]);
                ah[mt][1] = lds32h(&As[(rb + lr + 8) * 40 + kh + 2 * lc]);
                ah[mt][2] = lds32h(&As[(rb + lr) * 40 + kh + 2 * lc + 8]);
                ah[mt][3] = lds32h(&As[(rb + lr + 8) * 40 + kh + 2 * lc + 8]);
            }
            uint32_t bh[4][2];
#pragma unroll
            for (int nt = 0; nt < 4; nt++) {
                const int nb = wn * 32 + nt * 8;
                bh[nt][0] = lds32h(&Bs[(nb + lr) * 40 + kh + 2 * lc]);
                bh[nt][1] = lds32h(&Bs[(nb + lr) * 40 + kh + 2 * lc + 8]);
            }
#pragma unroll
            for (int mt = 0; mt < 4; mt++)
#pragma unroll
                for (int nt = 0; nt < 4; nt++)
                    mma16(c[mt][nt], ah[mt], bh[nt]);
        }
        __syncthreads();
    }
#undef ISSUE

    // epilogue
    const float* bias = (mat == 0) ? bq : ((mat == 1) ? bk : bv);
    __half* dstqk     = (mat == 0) ? g_q16 : g_k16;
    const bool rqk    = (mat != 2);
#pragma unroll
    for (int mt = 0; mt < 4; mt++) {
        const int m = m0 + wm * 64 + mt * 16 + lr;
#pragma unroll
        for (int nt = 0; nt < 4; nt++) {
            const int n = n0 + wn * 32 + nt * 8 + 2 * lc;
            const int hh = n >> 6, d = n & 63;
            const float b0 = bias[n], b1 = bias[n + 1];
#pragma unroll
            for (int half_ = 0; half_ < 2; half_++) {
                const int mm = m + half_ * 8;
                const int bi = mm >> 9, srow = mm & 511;
                float v0 = c[mt][nt][half_ * 2 + 0] + b0;
                float v1 = c[mt][nt][half_ * 2 + 1] + b1;
                if (rqk) {
                    __half2 hv = __floats2half2_rn(v0, v1);
                    *(__half2*)(dstqk + (((size_t)(bi * NH + hh)) * SEQ + srow) * DH + d) = hv;
                } else {
                    const float mv = mask[(size_t)bi * SEQ + srow];
                    __half* o = g_vt16 + ((size_t)(bi * NH + hh) * DH) * SEQ;
                    o[(size_t)d * SEQ + srow]       = __float2half(v0 * mv);
                    o[(size_t)(d + 1) * SEQ + srow] = __float2half(v1 * mv);
                }
            }
        }
    }
}

// ---------------------------------------------------------------------------
// Fused power-law attention, fp16 m16n8k16.
// 8 warps x 16 q-rows (q-tile 128); key-tile 32, double-buffered cp.async.
// Q fragments register-resident. Phase-1 accumulators pack DIRECTLY into
// phase-2 A fragments as half2 (no permutation needed for fp16 layout).
// V consumed transposed [d][s]; den from pre-fp16 fp32 u, quad-reduced.
// ---------------------------------------------------------------------------
#define KT 32
#define PADKH 72      // halves per K row (144 B)  -> banks 4*lr+lc distinct
#define PADVH 40      // halves per V row (80 B)   -> banks 20*lr+lc distinct
#define KBUF_H (KT * PADKH)
#define VBUF_H (DH * PADVH)

__global__ __launch_bounds__(256, 2) void attn_kernel(float* __restrict__ out)
{
    __shared__ __half Ks[2][KBUF_H];
    __shared__ __half Vs[2][VBUF_H];

    const int b  = blockIdx.z;
    const int h  = blockIdx.y;
    const int qt = blockIdx.x * 128;

    const __half* Qg = g_q16 + (((size_t)(b * NH + h)) * SEQ + qt) * DH;
    const __half* Kg = g_k16 + ((size_t)(b * NH + h)) * SEQ * DH;
    const __half* Vg = g_vt16 + ((size_t)(b * NH + h)) * DH * SEQ;   // [d][s]

    const int tid  = threadIdx.x;
    const int lane = tid & 31;
    const int wid  = tid >> 5;
    const int lr   = lane >> 2;
    const int lc   = lane & 3;

    // cp.async mappings
    const int krow = tid >> 3;              // 0..31 keys
    const int ksg  = (tid & 7) * 8;         // d segment (halves)
    const __half* KgR = Kg + (size_t)krow * DH + ksg;
    const uint32_t sK = smem_u32(&Ks[0][0]) + (uint32_t)(krow * PADKH + ksg) * 2;

    const int vrow = tid >> 2;              // 0..63 d
    const int vsg  = (tid & 3) * 8;         // key segment (halves)
    const __half* VgR = Vg + (size_t)vrow * SEQ + vsg;
    const uint32_t sV = smem_u32(&Vs[0][0]) + (uint32_t)(vrow * PADVH + vsg) * 2;

#define ISSKV(kt_, buf_)                                                      \
    do {                                                                      \
        const __half* _k = KgR + (size_t)(kt_) * KT * DH;                     \
        const __half* _v = VgR + (kt_) * KT;                                  \
        uint32_t _ok = (uint32_t)(buf_) * (KBUF_H * 2);                       \
        uint32_t _ov = (uint32_t)(buf_) * (VBUF_H * 2);                       \
        cpa16(sK + _ok, _k);                                                  \
        cpa16(sV + _ov, _v);                                                  \
        cpa_commit();                                                         \
    } while (0)

    ISSKV(0, 0);

    // Q fragments: 16 rows per warp, register-resident (4 ksteps x 4 regs)
    uint32_t qf[4][4];
    {
        const int r0 = wid * 16 + lr;
#pragma unroll
        for (int ks = 0; ks < 4; ks++) {
            const int dbase = ks * 16 + 2 * lc;
            qf[ks][0] = *(const uint32_t*)(Qg + (size_t)r0 * DH + dbase);
            qf[ks][1] = *(const uint32_t*)(Qg + (size_t)(r0 + 8) * DH + dbase);
            qf[ks][2] = *(const uint32_t*)(Qg + (size_t)r0 * DH + dbase + 8);
            qf[ks][3] = *(const uint32_t*)(Qg + (size_t)(r0 + 8) * DH + dbase + 8);
        }
    }

    float o[8][4];
#pragma unroll
    for (int j = 0; j < 8; j++)
#pragma unroll
        for (int q = 0; q < 4; q++) o[j][q] = 0.0f;
    float den0 = 0.0f, den1 = 0.0f;

    const int NKT = SEQ / KT;   // 16

    for (int kt = 0; kt < NKT; kt++) {
        const int buf = kt & 1;
        if (kt + 1 < NKT) {
            ISSKV(kt + 1, buf ^ 1);
            cpa_wait<1>();
        } else {
            cpa_wait<0>();
        }
        __syncthreads();

        const __half* Kb = Ks[buf];
        const __half* Vb = Vs[buf];

        // ---- phase 1: S = Q K^T  (d = 4 ksteps of k16; keys = 4 nt of n8) ----
        float s[4][4];
#pragma unroll
        for (int j = 0; j < 4; j++)
#pragma unroll
            for (int q = 0; q < 4; q++) s[j][q] = 0.0f;

#pragma unroll
        for (int ks = 0; ks < 4; ks++) {
            const int kh = ks * 16 + 2 * lc;
#pragma unroll
            for (int nt = 0; nt < 4; nt++) {
                uint32_t bb[2];
                bb[0] = lds32h(&Kb[(nt * 8 + lr) * PADKH + kh]);
                bb[1] = lds32h(&Kb[(nt * 8 + lr) * PADKH + kh + 8]);
                mma16(s[nt], qf[ks], bb);
            }
        }

        // ---- transform ----
        float u[4][4];
#pragma unroll
        for (int nt = 0; nt < 4; nt++) {
#pragma unroll
            for (int q = 0; q < 4; q++) {
                float t = fmaf(s[nt][q], 0.125f, 5.0f);
                u[nt][q] = t * t;
            }
            den0 += u[nt][0] + u[nt][1];
            den1 += u[nt][2] + u[nt][3];
        }

        // ---- phase 2: O += U * V  (keys = 2 ksteps of k16; d = 8 dt of n8) ----
#pragma unroll
        for (int ksp = 0; ksp < 2; ksp++) {
            uint32_t af[4];
            af[0] = pkh2(u[2 * ksp][0],     u[2 * ksp][1]);
            af[1] = pkh2(u[2 * ksp][2],     u[2 * ksp][3]);
            af[2] = pkh2(u[2 * ksp + 1][0], u[2 * ksp + 1][1]);
            af[3] = pkh2(u[2 * ksp + 1][2], u[2 * ksp + 1][3]);
            const int kh = ksp * 16 + 2 * lc;
#pragma unroll
            for (int dt = 0; dt < 8; dt++) {
                uint32_t bv[2];
                bv[0] = lds32h(&Vb[(dt * 8 + lr) * PADVH + kh]);
                bv[1] = lds32h(&Vb[(dt * 8 + lr) * PADVH + kh + 8]);
                mma16(o[dt], af, bv);
            }
        }
        __syncthreads();
    }
#undef ISSKV

    // quad-reduce den (lanes within quad cover disjoint key columns)
    den0 += __shfl_xor_sync(0xFFFFFFFFu, den0, 1);
    den0 += __shfl_xor_sync(0xFFFFFFFFu, den0, 2);
    den1 += __shfl_xor_sync(0xFFFFFFFFu, den1, 1);
    den1 += __shfl_xor_sync(0xFFFFFFFFu, den1, 2);

    const float inv0 = 1.0f / (den0 + 1e-10f);
    const float inv1 = 1.0f / (den1 + 1e-10f);
    const int r0 = qt + wid * 16 + lr;
    float* o0 = out + ((size_t)b * SEQ + r0) * DM + h * DH;
    float* o1 = out + ((size_t)b * SEQ + r0 + 8) * DM + h * DH;
#pragma unroll
    for (int dt = 0; dt < 8; dt++) {
        const int d = dt * 8 + 2 * lc;
        *(float2*)(o0 + d) = make_float2(o[dt][0] * inv0, o[dt][1] * inv0);
        *(float2*)(o1 + d) = make_float2(o[dt][2] * inv1, o[dt][3] * inv1);
    }
}

// ---------------------------------------------------------------------------
extern "C" void kernel_launch(void* const* d_in, const int* in_sizes, int n_in,
                              void* d_out, int out_size)
{
    const float* hidden = (const float*)d_in[0];
    const float* mask   = (const float*)d_in[1];
    const float* Wq     = (const float*)d_in[2];
    const float* bq     = (const float*)d_in[3];
    const float* Wk     = (const float*)d_in[4];
    const float* bk     = (const float*)d_in[5];
    const float* Wv     = (const float*)d_in[6];
    const float* bv     = (const float*)d_in[7];
    float* out = (float*)d_out;

    const int BS = in_sizes[1];
    const int B  = BS / SEQ;
    const int M  = BS;

    cudaFuncSetAttribute(qkv_gemm_kernel,
                         cudaFuncAttributeMaxDynamicSharedMemorySize, GEMM_SMEM);

    int n8 = M * DM / 8;
    hhalf_kernel<<<(n8 + 255) / 256, 256>>>(hidden, n8);

    dim3 gw(DM / 32, DM / 32, 3);
    wsplit_kernel<<<gw, dim3(32, 8)>>>(Wq, Wk, Wv);

    dim3 gm(M / 128, 18);
    qkv_gemm_kernel<<<gm, 256, GEMM_SMEM>>>(bq, bk, bv, mask, M);

    dim3 g2(SEQ / 128, NH, B);
    attn_kernel<<<g2, 256>>>(out);
}